// round 11
// baseline (speedup 1.0000x reference)
#include <cuda_runtime.h>
#include <math.h>
#include <stdint.h>

#define BATCH  8
#define SEQ    2048
#define MTOT   (BATCH*SEQ)      // 16384
#define DIN    64
#define HID    256
#define DMODEL 512
#define DINNER 1024
#define DSTATE 16
#define DTRANK 32
#define DCONV  4
#define DOUTD  64

// ---------------- fp32 scratch (consumed by conv/scan) ----------------
__device__ float g_xz   [MTOT*2*DINNER];   // (xm | z)
__device__ float g_xm   [MTOT*DINNER];
__device__ float g_dbl  [MTOT*64];         // [dt(32)|B(16)|C(16)]
__device__ float g_delta[MTOT*DINNER];

// ---------------- pre-rounded tf32 operands (hi/lo pairs or single) ----------------
__device__ float x_h [MTOT*DIN],    x_l [MTOT*DIN];
__device__ float h_h [MTOT*HID],    h_l [MTOT*HID];
__device__ float u_t [MTOT*DMODEL];
__device__ float xm_h[MTOT*DINNER], xm_l[MTOT*DINNER];
__device__ float db_h[MTOT*64],     db_l[MTOT*64];
__device__ float y_t [MTOT*DINNER];
__device__ float o1_h[MTOT*DMODEL], o1_l[MTOT*DMODEL];
__device__ float h2_h[MTOT*HID],    h2_l[MTOT*HID];
// weights
__device__ float w1_h[HID*DIN],        w1_l[HID*DIN];
__device__ float w2_h[DMODEL*HID],     w2_l[DMODEL*HID];
__device__ float wip_t[2*DINNER*DMODEL];
__device__ float wxp_h[64*DINNER],     wxp_l[64*DINNER];
__device__ float wdt_h[DINNER*DTRANK], wdt_l[DINNER*DTRANK];
__device__ float wop_t[DMODEL*DINNER];
__device__ float wd1_h[HID*DMODEL],    wd1_l[HID*DMODEL];
__device__ float wd2_h[DOUTD*HID],     wd2_l[DOUTD*HID];

enum Act { ACT_NONE = 0, ACT_RELU = 1, ACT_SOFTPLUS = 2 };
enum Epi { EPI_F32 = 0, EPI_HL = 1, EPI_T = 2, EPI_F32HL = 3 };

// ---------------- helpers ----------------
__device__ __forceinline__ float to_tf32(float x) {
    float r;
    asm("cvt.rna.tf32.f32 %0, %1;" : "=f"(r) : "f"(x));
    return r;
}

__device__ __forceinline__ void mma8(float c[4], const uint32_t a[4], const uint32_t b[2]) {
    asm volatile(
        "mma.sync.aligned.m16n8k8.row.col.f32.tf32.tf32.f32 "
        "{%0,%1,%2,%3}, {%4,%5,%6,%7}, {%8,%9}, {%0,%1,%2,%3};\n"
        : "+f"(c[0]), "+f"(c[1]), "+f"(c[2]), "+f"(c[3])
        : "r"(a[0]), "r"(a[1]), "r"(a[2]), "r"(a[3]),
          "r"(b[0]), "r"(b[1]));
}

__device__ __forceinline__ void cp16(void* sdst, const void* gsrc) {
    uint32_t d = (uint32_t)__cvta_generic_to_shared(sdst);
    asm volatile("cp.async.cg.shared.global [%0], [%1], 16;\n" :: "r"(d), "l"(gsrc));
}
__device__ __forceinline__ void cp_commit() { asm volatile("cp.async.commit_group;\n"); }
template<int N> __device__ __forceinline__ void cp_wait() {
    asm volatile("cp.async.wait_group %0;\n" :: "n"(N));
}

// ---------------- pipelined tf32-k8 GEMM (pre-rounded operands, zero in-loop cvt) ----
// C = act(A*W^T + bias); A rows pre-rounded (hi[,lo]); W rows pre-rounded (hi[,lo]).
// SPLIT: 3 MMAs per k8 (AhWh + AhWl + AlWh).
template<int BM,int BN,int WARPS_M,int WARPS_N,int ACT,int SPLIT,int EPI,int STAGES>
__global__ void __launch_bounds__(WARPS_M*WARPS_N*32)
gemm_pipe(const float* __restrict__ Ah, const float* __restrict__ Al,
          const float* __restrict__ Wh, const float* __restrict__ Wl,
          const float* __restrict__ bias,
          float* __restrict__ C0, float* __restrict__ C1, float* __restrict__ C2,
          int M, int N, int K, int lda)
{
    constexpr int BK = 32, SK = 36;
    constexpr int THREADS = WARPS_M*WARPS_N*32;
    constexpr int WM = BM/WARPS_M, WN = BN/WARPS_N;
    constexpr int MM = WM/16, MN = WN/8;
    constexpr int STAGE = (BM + BN) * SK * (SPLIT ? 2 : 1);

    extern __shared__ float smf[];

    const int tid  = threadIdx.x;
    const int lane = tid & 31;
    const int warp = tid >> 5;
    const int g    = lane >> 2;
    const int c4   = lane & 3;
    const int wrow = (warp / WARPS_N) * WM;
    const int wcol = (warp % WARPS_N) * WN;
    const int bm   = blockIdx.y * BM;
    const int bn   = blockIdx.x * BN;
    const int KT   = K / BK;

    float acc[MM][MN][4];
#pragma unroll
    for (int i = 0; i < MM; i++)
#pragma unroll
        for (int j = 0; j < MN; j++)
#pragma unroll
            for (int q = 0; q < 4; q++) acc[i][j][q] = 0.f;

    auto fill = [&](int kt) {
        if (kt < KT) {
            const int k0 = kt * BK;
            float* base = smf + (kt % STAGES) * STAGE;
            float* dAh = base;
            float* dWh = base + BM*SK;
#pragma unroll
            for (int i = tid; i < BM*8; i += THREADS) {
                int m = i >> 3, kc = (i & 7) * 4;
                cp16(dAh + m*SK + kc, Ah + (size_t)(bm + m)*lda + k0 + kc);
            }
#pragma unroll
            for (int i = tid; i < BN*8; i += THREADS) {
                int n = i >> 3, kc = (i & 7) * 4;
                cp16(dWh + n*SK + kc, Wh + (size_t)(bn + n)*K + k0 + kc);
            }
            if (SPLIT) {
                float* dAl = base + (BM+BN)*SK;
                float* dWl = dAl + BM*SK;
#pragma unroll
                for (int i = tid; i < BM*8; i += THREADS) {
                    int m = i >> 3, kc = (i & 7) * 4;
                    cp16(dAl + m*SK + kc, Al + (size_t)(bm + m)*lda + k0 + kc);
                }
#pragma unroll
                for (int i = tid; i < BN*8; i += THREADS) {
                    int n = i >> 3, kc = (i & 7) * 4;
                    cp16(dWl + n*SK + kc, Wl + (size_t)(bn + n)*K + k0 + kc);
                }
            }
        }
        cp_commit();
    };

    // prologue: stage tiles 0..STAGES-2
#pragma unroll
    for (int s = 0; s < STAGES-1; s++) fill(s);

    for (int kt = 0; kt < KT; kt++) {
        cp_wait<STAGES-2>();
        __syncthreads();
        fill(kt + STAGES - 1);     // refills buffer (kt-1)%S, safe after barrier

        const float* base = smf + (kt % STAGES) * STAGE;
        const float* sAh = base;
        const float* sWh = base + BM*SK;
        const float* sAl = base + (BM+BN)*SK;
        const float* sWl = sAl + BM*SK;

#pragma unroll
        for (int kk = 0; kk < BK; kk += 8) {
            uint32_t ah[MM][4], al[MM][4];
#pragma unroll
            for (int mi = 0; mi < MM; mi++) {
                const float* p = sAh + (wrow + mi*16 + g)*SK + kk + c4;
                ah[mi][0] = __float_as_uint(p[0]);
                ah[mi][1] = __float_as_uint(p[8*SK]);
                ah[mi][2] = __float_as_uint(p[4]);
                ah[mi][3] = __float_as_uint(p[8*SK + 4]);
                if (SPLIT) {
                    const float* q = sAl + (wrow + mi*16 + g)*SK + kk + c4;
                    al[mi][0] = __float_as_uint(q[0]);
                    al[mi][1] = __float_as_uint(q[8*SK]);
                    al[mi][2] = __float_as_uint(q[4]);
                    al[mi][3] = __float_as_uint(q[8*SK + 4]);
                }
            }
#pragma unroll
            for (int ni = 0; ni < MN; ni++) {
                const float* p = sWh + (wcol + ni*8 + g)*SK + kk + c4;
                uint32_t bh[2] = { __float_as_uint(p[0]), __float_as_uint(p[4]) };
                uint32_t bl[2];
                if (SPLIT) {
                    const float* q = sWl + (wcol + ni*8 + g)*SK + kk + c4;
                    bl[0] = __float_as_uint(q[0]);
                    bl[1] = __float_as_uint(q[4]);
                }
#pragma unroll
                for (int mi = 0; mi < MM; mi++) {
                    if (SPLIT) {
                        mma8(acc[mi][ni], al[mi], bh);
                        mma8(acc[mi][ni], ah[mi], bl);
                    }
                    mma8(acc[mi][ni], ah[mi], bh);
                }
            }
        }
        __syncthreads();
    }

    // ---- epilogue ----
#pragma unroll
    for (int mi = 0; mi < MM; mi++) {
        int r0 = bm + wrow + mi*16 + g;
#pragma unroll
        for (int ni = 0; ni < MN; ni++) {
            int col = bn + wcol + ni*8 + 2*c4;
            float b0 = 0.f, b1 = 0.f;
            if (bias) { b0 = bias[col]; b1 = bias[col + 1]; }
            float v[4];
            v[0] = acc[mi][ni][0] + b0;
            v[1] = acc[mi][ni][1] + b1;
            v[2] = acc[mi][ni][2] + b0;
            v[3] = acc[mi][ni][3] + b1;
#pragma unroll
            for (int q = 0; q < 4; q++) {
                if (ACT == ACT_RELU)     v[q] = fmaxf(v[q], 0.f);
                if (ACT == ACT_SOFTPLUS) v[q] = (v[q] > 20.f) ? v[q] : log1pf(__expf(v[q]));
            }
            size_t i0 = (size_t)r0*N + col;
            size_t i1 = (size_t)(r0 + 8)*N + col;
            if (EPI == EPI_F32) {
                *(float2*)(C0 + i0) = make_float2(v[0], v[1]);
                *(float2*)(C0 + i1) = make_float2(v[2], v[3]);
            } else if (EPI == EPI_T) {
                *(float2*)(C0 + i0) = make_float2(to_tf32(v[0]), to_tf32(v[1]));
                *(float2*)(C0 + i1) = make_float2(to_tf32(v[2]), to_tf32(v[3]));
            } else {
                float hi[4], lo[4];
#pragma unroll
                for (int q = 0; q < 4; q++) {
                    hi[q] = to_tf32(v[q]);
                    lo[q] = to_tf32(v[q] - hi[q]);
                }
                if (EPI == EPI_F32HL) {
                    *(float2*)(C0 + i0) = make_float2(v[0], v[1]);
                    *(float2*)(C0 + i1) = make_float2(v[2], v[3]);
                    *(float2*)(C1 + i0) = make_float2(hi[0], hi[1]);
                    *(float2*)(C1 + i1) = make_float2(hi[2], hi[3]);
                    *(float2*)(C2 + i0) = make_float2(lo[0], lo[1]);
                    *(float2*)(C2 + i1) = make_float2(lo[2], lo[3]);
                } else { // EPI_HL
                    *(float2*)(C0 + i0) = make_float2(hi[0], hi[1]);
                    *(float2*)(C0 + i1) = make_float2(hi[2], hi[3]);
                    *(float2*)(C1 + i0) = make_float2(lo[0], lo[1]);
                    *(float2*)(C1 + i1) = make_float2(lo[2], lo[3]);
                }
            }
        }
    }
}

// ---------------- converters (run once per launch; tiny) ----------------
__global__ void cvt_split_kernel(const float* __restrict__ s,
                                 float* __restrict__ h, float* __restrict__ l, int n)
{
    int i = blockIdx.x * blockDim.x + threadIdx.x;
    if (i < n) {
        float v = s[i];
        float hv = to_tf32(v);
        h[i] = hv;
        l[i] = to_tf32(v - hv);
    }
}
__global__ void cvt_t_kernel(const float* __restrict__ s, float* __restrict__ d, int n)
{
    int i = blockIdx.x * blockDim.x + threadIdx.x;
    if (i < n) d[i] = to_tf32(s[i]);
}

// ---------------- depthwise causal conv1d + bias + SiLU (+ tf32 hi/lo out) ----------
__global__ void conv_silu_kernel(const float* __restrict__ conv_w,
                                 const float* __restrict__ conv_b)
{
    int idx = blockIdx.x * blockDim.x + threadIdx.x;
    if (idx >= MTOT * DINNER) return;
    int d  = idx % DINNER;
    int bt = idx / DINNER;
    int t  = bt % SEQ;
    int b  = bt / SEQ;

    float acc = conv_b[d];
#pragma unroll
    for (int j = 0; j < DCONV; j++) {
        int tt = t - (DCONV - 1) + j;
        if (tt >= 0)
            acc = fmaf(conv_w[d*DCONV + j],
                       g_xz[(size_t)(b*SEQ + tt)*(2*DINNER) + d], acc);
    }
    float sv = acc / (1.f + __expf(-acc));
    size_t o = (size_t)bt*DINNER + d;
    g_xm[o] = sv;
    float hv = to_tf32(sv);
    xm_h[o] = hv;
    xm_l[o] = to_tf32(sv - hv);
}

// ---------------- selective scan + fused gating (tf32 out) ----------------
__global__ void scan_kernel(const float* __restrict__ A_log,
                            const float* __restrict__ D_param)
{
    int gid = blockIdx.x * blockDim.x + threadIdx.x;
    int grp = gid >> 4;          // (b,d)
    int s   = gid & 15;
    if (grp >= BATCH * DINNER) return;
    int b = grp / DINNER;
    int d = grp % DINNER;

    const float Av = -__expf(A_log[d*DSTATE + s]);
    const float Dv = D_param[d];
    const float* drow = g_delta + (size_t)b*SEQ*DINNER + d;
    const float* xrow = g_xm    + (size_t)b*SEQ*DINNER + d;
    const float* zrow = g_xz    + (size_t)b*SEQ*(2*DINNER) + DINNER + d;
    const float* dblb = g_dbl   + (size_t)b*SEQ*64;
    float*       yrow = y_t     + (size_t)b*SEQ*DINNER + d;

    float h = 0.f;
    for (int t = 0; t < SEQ; t++) {
        float dt = drow[(size_t)t*DINNER];
        float xt = xrow[(size_t)t*DINNER];
        float Bt = dblb[t*64 + DTRANK + s];
        float Ct = dblb[t*64 + DTRANK + DSTATE + s];
        float dA = __expf(dt * Av);
        h = fmaf(dA, h, dt * xt * Bt);
        float p = h * Ct;
        p += __shfl_xor_sync(0xffffffffu, p, 8, 16);
        p += __shfl_xor_sync(0xffffffffu, p, 4, 16);
        p += __shfl_xor_sync(0xffffffffu, p, 2, 16);
        p += __shfl_xor_sync(0xffffffffu, p, 1, 16);
        if (s == 0) {
            float z  = zrow[(size_t)t*2*DINNER];
            float yv = p + xt * Dv;
            yrow[(size_t)t*DINNER] = to_tf32(yv * (z / (1.f + __expf(-z))));
        }
    }
}

// ---------------- host launch ----------------
static float* sym_addr(const void* symbol)
{
    void* p = nullptr;
    cudaGetSymbolAddress(&p, symbol);
    return (float*)p;
}

extern "C" void kernel_launch(void* const* d_in, const int* in_sizes, int n_in,
                              void* d_out, int out_size)
{
    const float* x         = (const float*)d_in[0];
    const float* enc_w1    = (const float*)d_in[1];
    const float* enc_b1    = (const float*)d_in[2];
    const float* enc_w2    = (const float*)d_in[3];
    const float* enc_b2    = (const float*)d_in[4];
    const float* in_proj_w = (const float*)d_in[5];
    const float* conv_w    = (const float*)d_in[6];
    const float* conv_b    = (const float*)d_in[7];
    const float* x_proj_w  = (const float*)d_in[8];
    const float* dt_proj_w = (const float*)d_in[9];
    const float* dt_proj_b = (const float*)d_in[10];
    const float* A_log     = (const float*)d_in[11];
    const float* D_param   = (const float*)d_in[12];
    const float* out_proj_w= (const float*)d_in[13];
    const float* dec_w1    = (const float*)d_in[14];
    const float* dec_b1    = (const float*)d_in[15];
    const float* dec_w2    = (const float*)d_in[16];
    const float* dec_b2    = (const float*)d_in[17];
    float* out = (float*)d_out;

    float* pxz  = sym_addr(g_xz);
    float* pdbl = sym_addr(g_dbl);
    float* pdel = sym_addr(g_delta);
    float* pxh  = sym_addr(x_h),  * pxl  = sym_addr(x_l);
    float* phh  = sym_addr(h_h),  * phl  = sym_addr(h_l);
    float* put  = sym_addr(u_t);
    float* pxmh = sym_addr(xm_h), * pxml = sym_addr(xm_l);
    float* pdbh = sym_addr(db_h), * pdbll= sym_addr(db_l);
    float* pyt  = sym_addr(y_t);
    float* po1h = sym_addr(o1_h), * po1l = sym_addr(o1_l);
    float* ph2h = sym_addr(h2_h), * ph2l = sym_addr(h2_l);
    float* pw1h = sym_addr(w1_h), * pw1l = sym_addr(w1_l);
    float* pw2h = sym_addr(w2_h), * pw2l = sym_addr(w2_l);
    float* pwip = sym_addr(wip_t);
    float* pwxh = sym_addr(wxp_h),* pwxl = sym_addr(wxp_l);
    float* pwdh = sym_addr(wdt_h),* pwdl = sym_addr(wdt_l);
    float* pwop = sym_addr(wop_t);
    float* pd1h = sym_addr(wd1_h),* pd1l = sym_addr(wd1_l);
    float* pd2h = sym_addr(wd2_h),* pd2l = sym_addr(wd2_l);

    // smem sizes
    const int SM_SPLIT_128 = 3 * (128+128)*36*2*4;   // 221184
    const int SM_SPLIT_64  = 3 * (128+64)*36*2*4;    // 165888
    const int SM_PLAIN_128 = 4 * (128+128)*36*4;     // 147456

    cudaFuncSetAttribute((const void*)gemm_pipe<128,128,2,4,ACT_RELU,1,EPI_HL,3>,
                         cudaFuncAttributeMaxDynamicSharedMemorySize, SM_SPLIT_128);
    cudaFuncSetAttribute((const void*)gemm_pipe<128,128,2,4,ACT_NONE,1,EPI_T,3>,
                         cudaFuncAttributeMaxDynamicSharedMemorySize, SM_SPLIT_128);
    cudaFuncSetAttribute((const void*)gemm_pipe<128,128,2,4,ACT_NONE,0,EPI_F32,4>,
                         cudaFuncAttributeMaxDynamicSharedMemorySize, SM_PLAIN_128);
    cudaFuncSetAttribute((const void*)gemm_pipe<128,64,4,2,ACT_NONE,1,EPI_F32HL,3>,
                         cudaFuncAttributeMaxDynamicSharedMemorySize, SM_SPLIT_64);
    cudaFuncSetAttribute((const void*)gemm_pipe<128,128,2,4,ACT_SOFTPLUS,1,EPI_F32,3>,
                         cudaFuncAttributeMaxDynamicSharedMemorySize, SM_SPLIT_128);
    cudaFuncSetAttribute((const void*)gemm_pipe<128,128,2,4,ACT_NONE,0,EPI_HL,4>,
                         cudaFuncAttributeMaxDynamicSharedMemorySize, SM_PLAIN_128);
    cudaFuncSetAttribute((const void*)gemm_pipe<128,64,4,2,ACT_NONE,1,EPI_F32,3>,
                         cudaFuncAttributeMaxDynamicSharedMemorySize, SM_SPLIT_64);

    // ---- converters ----
    auto cvs = [&](const float* s, float* h, float* l, int n) {
        cvt_split_kernel<<<(n + 255)/256, 256>>>(s, h, l, n);
    };
    cvs(x,        pxh,  pxl,  MTOT*DIN);
    cvs(enc_w1,   pw1h, pw1l, HID*DIN);
    cvs(enc_w2,   pw2h, pw2l, DMODEL*HID);
    cvs(x_proj_w, pwxh, pwxl, 64*DINNER);
    cvs(dt_proj_w,pwdh, pwdl, DINNER*DTRANK);
    cvs(dec_w1,   pd1h, pd1l, HID*DMODEL);
    cvs(dec_w2,   pd2h, pd2l, DOUTD*HID);
    cvt_t_kernel<<<(2*DINNER*DMODEL + 255)/256, 256>>>(in_proj_w,  pwip, 2*DINNER*DMODEL);
    cvt_t_kernel<<<(DMODEL*DINNER + 255)/256, 256>>>(out_proj_w, pwop, DMODEL*DINNER);

    // 1. enc1: relu -> h (hi/lo)          [16384,256] K=64
    gemm_pipe<128,128,2,4,ACT_RELU,1,EPI_HL,3><<<dim3(HID/128, MTOT/128), 256, SM_SPLIT_128>>>(
        pxh, pxl, pw1h, pw1l, enc_b1, phh, phl, nullptr, MTOT, HID, DIN, DIN);

    // 2. enc2: u (tf32)                   [16384,512] K=256
    gemm_pipe<128,128,2,4,ACT_NONE,1,EPI_T,3><<<dim3(DMODEL/128, MTOT/128), 256, SM_SPLIT_128>>>(
        phh, phl, pw2h, pw2l, enc_b2, put, nullptr, nullptr, MTOT, DMODEL, HID, HID);

    // 3. in_proj: xz (fp32)               [16384,2048] K=512 (plain tf32)
    gemm_pipe<128,128,2,4,ACT_NONE,0,EPI_F32,4><<<dim3(2*DINNER/128, MTOT/128), 256, SM_PLAIN_128>>>(
        put, nullptr, pwip, nullptr, nullptr, pxz, nullptr, nullptr, MTOT, 2*DINNER, DMODEL, DMODEL);

    // 4. conv + bias + silu -> g_xm + xm hi/lo
    conv_silu_kernel<<<(MTOT*DINNER)/256, 256>>>(conv_w, conv_b);

    // 5. x_proj: dbl (fp32 + hi/lo)       [16384,64] K=1024
    gemm_pipe<128,64,4,2,ACT_NONE,1,EPI_F32HL,3><<<dim3(1, MTOT/128), 256, SM_SPLIT_64>>>(
        pxmh, pxml, pwxh, pwxl, nullptr, pdbl, pdbh, pdbll, MTOT, 64, DINNER, DINNER);

    // 6. dt_proj + softplus: delta (fp32) [16384,1024] K=32, lda=64
    gemm_pipe<128,128,2,4,ACT_SOFTPLUS,1,EPI_F32,3><<<dim3(DINNER/128, MTOT/128), 256, SM_SPLIT_128>>>(
        pdbh, pdbll, pwdh, pwdl, dt_proj_b, pdel, nullptr, nullptr, MTOT, DINNER, DTRANK, 64);

    // 7. selective scan + fused gating -> y_t (tf32)
    scan_kernel<<<(BATCH*DINNER*DSTATE)/256, 256>>>(A_log, D_param);

    // 8. out_proj: o1 (hi/lo)             [16384,512] K=1024 (plain tf32)
    gemm_pipe<128,128,2,4,ACT_NONE,0,EPI_HL,4><<<dim3(DMODEL/128, MTOT/128), 256, SM_PLAIN_128>>>(
        pyt, nullptr, pwop, nullptr, nullptr, po1h, po1l, nullptr, MTOT, DMODEL, DINNER, DINNER);

    // 9. dec1: relu -> h2 (hi/lo)         [16384,256] K=512
    gemm_pipe<128,128,2,4,ACT_RELU,1,EPI_HL,3><<<dim3(HID/128, MTOT/128), 256, SM_SPLIT_128>>>(
        po1h, po1l, pd1h, pd1l, dec_b1, ph2h, ph2l, nullptr, MTOT, HID, DMODEL, DMODEL);

    // 10. dec2 -> out (fp32)              [16384,64] K=256
    gemm_pipe<128,64,4,2,ACT_NONE,1,EPI_F32,3><<<dim3(1, MTOT/128), 256, SM_SPLIT_64>>>(
        ph2h, ph2l, pd2h, pd2l, dec_b2, out, nullptr, nullptr, MTOT, DOUTD, HID, HID);
}

// round 13
// speedup vs baseline: 1.5286x; 1.5286x over previous
#include <cuda_runtime.h>
#include <cuda_bf16.h>
#include <cuda_fp16.h>
#include <math.h>
#include <stdint.h>

#define BATCH  8
#define SEQ    2048
#define MTOT   (BATCH*SEQ)      // 16384
#define DIN    64
#define HID    256
#define DMODEL 512
#define DINNER 1024
#define DSTATE 16
#define DTRANK 32
#define DCONV  4
#define DOUTD  64

typedef unsigned short u16;

// ---------------- fp32 scratch ----------------
__device__ float g_xz   [MTOT*2*DINNER];   // (xm | z)
__device__ float g_xm   [MTOT*DINNER];
__device__ float g_dbl  [MTOT*64];         // [dt(32)|B(16)|C(16)]
__device__ float g_delta[MTOT*DINNER];

// ---------------- 16-bit pre-converted operands ----------------
__device__ u16 x_h [MTOT*DIN],    x_l [MTOT*DIN];      // bf16 hi/lo
__device__ u16 h_h [MTOT*HID],    h_l [MTOT*HID];
__device__ u16 u_s [MTOT*DMODEL];                      // fp16 * 1024
__device__ u16 xm_hb[MTOT*DINNER], xm_lb[MTOT*DINNER];
__device__ u16 db_hb[MTOT*64],     db_lb[MTOT*64];
__device__ u16 y_s [MTOT*DINNER];                      // fp16 * 4096
__device__ u16 o1_hb[MTOT*DMODEL], o1_lb[MTOT*DMODEL];
__device__ u16 h2_hb[MTOT*HID],    h2_lb[MTOT*HID];
// weights
__device__ u16 w1_hb[HID*DIN],        w1_lb[HID*DIN];
__device__ u16 w2_hb[DMODEL*HID],     w2_lb[DMODEL*HID];
__device__ u16 wip_s[2*DINNER*DMODEL];                 // fp16 * 64
__device__ u16 wxp_hb[64*DINNER],     wxp_lb[64*DINNER];
__device__ u16 wdt_hb[DINNER*DTRANK], wdt_lb[DINNER*DTRANK];
__device__ u16 wop_s[DMODEL*DINNER];                   // fp16 * 64
__device__ u16 wd1_hb[HID*DMODEL],    wd1_lb[HID*DMODEL];
__device__ u16 wd2_hb[DOUTD*HID],     wd2_lb[DOUTD*HID];

enum Act { ACT_NONE = 0, ACT_RELU = 1, ACT_SOFTPLUS = 2 };
enum Epi { EPI_F32 = 0, EPI_BFHL = 1, EPI_FP16S = 2, EPI_F32_BFHL = 3 };

// ---------------- helpers ----------------
__device__ __forceinline__ u16 f2bf(float v) {
    __nv_bfloat16 b = __float2bfloat16(v);
    return *(u16*)&b;
}
__device__ __forceinline__ float bf2f(u16 b) {
    __nv_bfloat16 t = *(__nv_bfloat16*)&b;
    return __bfloat162float(t);
}
__device__ __forceinline__ u16 f2h(float v) {
    __half h = __float2half_rn(v);
    return *(u16*)&h;
}

__device__ __forceinline__ void mma16_bf(float c[4], const uint32_t a[4], const uint32_t b[2]) {
    asm volatile(
        "mma.sync.aligned.m16n8k16.row.col.f32.bf16.bf16.f32 "
        "{%0,%1,%2,%3}, {%4,%5,%6,%7}, {%8,%9}, {%0,%1,%2,%3};\n"
        : "+f"(c[0]), "+f"(c[1]), "+f"(c[2]), "+f"(c[3])
        : "r"(a[0]), "r"(a[1]), "r"(a[2]), "r"(a[3]), "r"(b[0]), "r"(b[1]));
}
__device__ __forceinline__ void mma16_fp(float c[4], const uint32_t a[4], const uint32_t b[2]) {
    asm volatile(
        "mma.sync.aligned.m16n8k16.row.col.f32.f16.f16.f32 "
        "{%0,%1,%2,%3}, {%4,%5,%6,%7}, {%8,%9}, {%0,%1,%2,%3};\n"
        : "+f"(c[0]), "+f"(c[1]), "+f"(c[2]), "+f"(c[3])
        : "r"(a[0]), "r"(a[1]), "r"(a[2]), "r"(a[3]), "r"(b[0]), "r"(b[1]));
}
__device__ __forceinline__ void ldsm4(uint32_t* r, uint32_t saddr) {
    asm volatile("ldmatrix.sync.aligned.m8n8.x4.shared.b16 {%0,%1,%2,%3}, [%4];"
                 : "=r"(r[0]), "=r"(r[1]), "=r"(r[2]), "=r"(r[3]) : "r"(saddr));
}
__device__ __forceinline__ void cp16(void* sdst, const void* gsrc) {
    uint32_t d = (uint32_t)__cvta_generic_to_shared(sdst);
    asm volatile("cp.async.cg.shared.global [%0], [%1], 16;\n" :: "r"(d), "l"(gsrc));
}
__device__ __forceinline__ void cp_commit() { asm volatile("cp.async.commit_group;\n"); }
template<int N> __device__ __forceinline__ void cp_wait() {
    asm volatile("cp.async.wait_group %0;\n" :: "n"(N));
}

// ---------------- cp.async multi-stage 16-bit GEMM ----------------
// C = act(inv_s * A*W^T + bias). Operands pre-converted in global (16-bit).
// SPLIT=1: bf16 hi/lo, 3 bf16 MMAs per k16. SPLIT=0: scaled fp16, 1 MMA.
template<int BM,int BN,int WARPS_M,int WARPS_N,int ACT,int SPLIT,int EPI,int STAGES>
__global__ void __launch_bounds__(WARPS_M*WARPS_N*32, 2)
gemm16(const u16* __restrict__ Ah, const u16* __restrict__ Al,
       const u16* __restrict__ Wh, const u16* __restrict__ Wl,
       const float* __restrict__ bias,
       void* C0v, void* C1v, void* C2v,
       int M, int N, int K, int lda, float inv_s, float oscale)
{
    constexpr int BK = 32, SK2 = 40;
    constexpr int THREADS = WARPS_M*WARPS_N*32;
    constexpr int WMt = BM/WARPS_M, WNt = BN/WARPS_N;
    constexpr int MM = WMt/16, MN = WNt/8;
    constexpr int A_SH = BM*SK2, B_SH = BN*SK2;
    constexpr int STAGE = (A_SH + B_SH) * (SPLIT ? 2 : 1);
    static_assert(MN % 2 == 0, "MN even");

    extern __shared__ u16 sm16[];

    const int tid  = threadIdx.x;
    const int lane = tid & 31;
    const int warp = tid >> 5;
    const int g    = lane >> 2;
    const int c4   = lane & 3;
    const int wrow = (warp / WARPS_N) * WMt;
    const int wcol = (warp % WARPS_N) * WNt;
    const int bm   = blockIdx.y * BM;
    const int bn   = blockIdx.x * BN;
    const int KT   = K / BK;

    // ldmatrix lane mapping (R9-proven)
    const int a_m  = lane & 15;
    const int a_kc = (lane & 16) >> 1;
    const int b_nt = (lane >> 4) & 1;
    const int b_n  = lane & 7;
    const int b_kc = lane & 8;

    float acc[MM][MN][4];
#pragma unroll
    for (int i = 0; i < MM; i++)
#pragma unroll
        for (int j = 0; j < MN; j++)
#pragma unroll
            for (int q = 0; q < 4; q++) acc[i][j][q] = 0.f;

    auto fill = [&](int kt) {
        if (kt < KT) {
            const int k0 = kt * BK;
            u16* base = sm16 + (kt % STAGES) * STAGE;
            u16* dA = base;
            u16* dB = base + A_SH;
#pragma unroll
            for (int i = tid; i < BM*4; i += THREADS) {
                int r = i >> 2, c = (i & 3) * 8;
                cp16(dA + r*SK2 + c, Ah + (size_t)(bm + r)*lda + k0 + c);
            }
#pragma unroll
            for (int i = tid; i < BN*4; i += THREADS) {
                int r = i >> 2, c = (i & 3) * 8;
                cp16(dB + r*SK2 + c, Wh + (size_t)(bn + r)*K + k0 + c);
            }
            if (SPLIT) {
                u16* dAl = base + A_SH + B_SH;
                u16* dBl = dAl + A_SH;
#pragma unroll
                for (int i = tid; i < BM*4; i += THREADS) {
                    int r = i >> 2, c = (i & 3) * 8;
                    cp16(dAl + r*SK2 + c, Al + (size_t)(bm + r)*lda + k0 + c);
                }
#pragma unroll
                for (int i = tid; i < BN*4; i += THREADS) {
                    int r = i >> 2, c = (i & 3) * 8;
                    cp16(dBl + r*SK2 + c, Wl + (size_t)(bn + r)*K + k0 + c);
                }
            }
        }
        cp_commit();
    };

#pragma unroll
    for (int s = 0; s < STAGES-1; s++) fill(s);

    for (int kt = 0; kt < KT; kt++) {
        cp_wait<STAGES-2>();
        __syncthreads();
        fill(kt + STAGES - 1);

        u16* base = sm16 + (kt % STAGES) * STAGE;
        const uint32_t sAh = (uint32_t)__cvta_generic_to_shared(base);
        const uint32_t sBh = sAh + A_SH*2;
        const uint32_t sAl = sBh + B_SH*2;
        const uint32_t sBl = sAl + A_SH*2;

#pragma unroll
        for (int kk = 0; kk < BK; kk += 16) {
            uint32_t ah[MM][4], al[MM][4];
#pragma unroll
            for (int mi = 0; mi < MM; mi++) {
                uint32_t off = (uint32_t)(((wrow + mi*16 + a_m)*SK2 + kk + a_kc) * 2);
                ldsm4(ah[mi], sAh + off);
                if (SPLIT) ldsm4(al[mi], sAl + off);
            }
            uint32_t bh[MN][2], bl[MN][2];
#pragma unroll
            for (int ni = 0; ni < MN; ni += 2) {
                uint32_t off = (uint32_t)(((wcol + (ni + b_nt)*8 + b_n)*SK2 + kk + b_kc) * 2);
                uint32_t rh[4];
                ldsm4(rh, sBh + off);
                bh[ni][0] = rh[0];   bh[ni][1] = rh[1];
                bh[ni+1][0] = rh[2]; bh[ni+1][1] = rh[3];
                if (SPLIT) {
                    uint32_t rl[4];
                    ldsm4(rl, sBl + off);
                    bl[ni][0] = rl[0];   bl[ni][1] = rl[1];
                    bl[ni+1][0] = rl[2]; bl[ni+1][1] = rl[3];
                }
            }
#pragma unroll
            for (int ni = 0; ni < MN; ni++)
#pragma unroll
                for (int mi = 0; mi < MM; mi++) {
                    if (SPLIT) {
                        mma16_bf(acc[mi][ni], al[mi], bh[ni]);
                        mma16_bf(acc[mi][ni], ah[mi], bl[ni]);
                        mma16_bf(acc[mi][ni], ah[mi], bh[ni]);
                    } else {
                        mma16_fp(acc[mi][ni], ah[mi], bh[ni]);
                    }
                }
        }
        __syncthreads();
    }

    // ---- epilogue ----
#pragma unroll
    for (int mi = 0; mi < MM; mi++) {
        int r0 = bm + wrow + mi*16 + g;
#pragma unroll
        for (int ni = 0; ni < MN; ni++) {
            int col = bn + wcol + ni*8 + 2*c4;
            float b0 = 0.f, b1 = 0.f;
            if (bias) { b0 = bias[col]; b1 = bias[col + 1]; }
            float v[4];
            v[0] = acc[mi][ni][0]*inv_s + b0;
            v[1] = acc[mi][ni][1]*inv_s + b1;
            v[2] = acc[mi][ni][2]*inv_s + b0;
            v[3] = acc[mi][ni][3]*inv_s + b1;
#pragma unroll
            for (int q = 0; q < 4; q++) {
                if (ACT == ACT_RELU)     v[q] = fmaxf(v[q], 0.f);
                if (ACT == ACT_SOFTPLUS) v[q] = (v[q] > 20.f) ? v[q] : log1pf(__expf(v[q]));
            }
            size_t i0 = (size_t)r0*N + col;
            size_t i1 = (size_t)(r0 + 8)*N + col;
            if (EPI == EPI_F32) {
                float* C0 = (float*)C0v;
                *(float2*)(C0 + i0) = make_float2(v[0], v[1]);
                *(float2*)(C0 + i1) = make_float2(v[2], v[3]);
            } else if (EPI == EPI_FP16S) {
                u16* C0 = (u16*)C0v;
                *(uint32_t*)(C0 + i0) = (uint32_t)f2h(v[0]*oscale) | ((uint32_t)f2h(v[1]*oscale) << 16);
                *(uint32_t*)(C0 + i1) = (uint32_t)f2h(v[2]*oscale) | ((uint32_t)f2h(v[3]*oscale) << 16);
            } else {
                u16 hi[4], lo[4];
#pragma unroll
                for (int q = 0; q < 4; q++) {
                    hi[q] = f2bf(v[q]);
                    lo[q] = f2bf(v[q] - bf2f(hi[q]));
                }
                u16* CH = (u16*)((EPI == EPI_F32_BFHL) ? C1v : C0v);
                u16* CL = (u16*)((EPI == EPI_F32_BFHL) ? C2v : C1v);
                *(uint32_t*)(CH + i0) = (uint32_t)hi[0] | ((uint32_t)hi[1] << 16);
                *(uint32_t*)(CH + i1) = (uint32_t)hi[2] | ((uint32_t)hi[3] << 16);
                *(uint32_t*)(CL + i0) = (uint32_t)lo[0] | ((uint32_t)lo[1] << 16);
                *(uint32_t*)(CL + i1) = (uint32_t)lo[2] | ((uint32_t)lo[3] << 16);
                if (EPI == EPI_F32_BFHL) {
                    float* C0 = (float*)C0v;
                    *(float2*)(C0 + i0) = make_float2(v[0], v[1]);
                    *(float2*)(C0 + i1) = make_float2(v[2], v[3]);
                }
            }
        }
    }
}

// ---------------- converters ----------------
__global__ void cvt_bf(const float* __restrict__ s, u16* __restrict__ h,
                       u16* __restrict__ l, int n)
{
    int i = blockIdx.x * blockDim.x + threadIdx.x;
    if (i < n) {
        float v = s[i];
        u16 hb = f2bf(v);
        h[i] = hb;
        l[i] = f2bf(v - bf2f(hb));
    }
}
__global__ void cvt_h(const float* __restrict__ s, u16* __restrict__ d,
                      float scale, int n)
{
    int i = blockIdx.x * blockDim.x + threadIdx.x;
    if (i < n) d[i] = f2h(s[i] * scale);
}

// ---------------- conv1d + bias + SiLU -> fp32 + bf16 hi/lo ----------------
__global__ void conv_silu_kernel(const float* __restrict__ conv_w,
                                 const float* __restrict__ conv_b)
{
    int idx = blockIdx.x * blockDim.x + threadIdx.x;
    if (idx >= MTOT * DINNER) return;
    int d  = idx % DINNER;
    int bt = idx / DINNER;
    int t  = bt % SEQ;
    int b  = bt / SEQ;

    float acc = conv_b[d];
#pragma unroll
    for (int j = 0; j < DCONV; j++) {
        int tt = t - (DCONV - 1) + j;
        if (tt >= 0)
            acc = fmaf(conv_w[d*DCONV + j],
                       g_xz[(size_t)(b*SEQ + tt)*(2*DINNER) + d], acc);
    }
    float sv = acc / (1.f + __expf(-acc));
    size_t o = (size_t)bt*DINNER + d;
    g_xm[o] = sv;
    u16 hb = f2bf(sv);
    xm_hb[o] = hb;
    xm_lb[o] = f2bf(sv - bf2f(hb));
}

// ---------------- selective scan + fused gating -> scaled fp16 ----------------
__global__ void scan_kernel(const float* __restrict__ A_log,
                            const float* __restrict__ D_param)
{
    int gid = blockIdx.x * blockDim.x + threadIdx.x;
    int grp = gid >> 4;
    int s   = gid & 15;
    if (grp >= BATCH * DINNER) return;
    int b = grp / DINNER;
    int d = grp % DINNER;

    const float Av = -__expf(A_log[d*DSTATE + s]);
    const float Dv = D_param[d];
    const float* drow = g_delta + (size_t)b*SEQ*DINNER + d;
    const float* xrow = g_xm    + (size_t)b*SEQ*DINNER + d;
    const float* zrow = g_xz    + (size_t)b*SEQ*(2*DINNER) + DINNER + d;
    const float* dblb = g_dbl   + (size_t)b*SEQ*64;
    u16*         yrow = y_s     + (size_t)b*SEQ*DINNER + d;

    float h = 0.f;
    for (int t = 0; t < SEQ; t++) {
        float dt = drow[(size_t)t*DINNER];
        float xt = xrow[(size_t)t*DINNER];
        float Bt = dblb[t*64 + DTRANK + s];
        float Ct = dblb[t*64 + DTRANK + DSTATE + s];
        float dA = __expf(dt * Av);
        h = fmaf(dA, h, dt * xt * Bt);
        float p = h * Ct;
        p += __shfl_xor_sync(0xffffffffu, p, 8, 16);
        p += __shfl_xor_sync(0xffffffffu, p, 4, 16);
        p += __shfl_xor_sync(0xffffffffu, p, 2, 16);
        p += __shfl_xor_sync(0xffffffffu, p, 1, 16);
        if (s == 0) {
            float z  = zrow[(size_t)t*2*DINNER];
            float yv = p + xt * Dv;
            yrow[(size_t)t*DINNER] = f2h(yv * (z / (1.f + __expf(-z))) * 4096.f);
        }
    }
}

// ---------------- host launch ----------------
static void* sym_addr(const void* symbol)
{
    void* p = nullptr;
    cudaGetSymbolAddress(&p, symbol);
    return p;
}

extern "C" void kernel_launch(void* const* d_in, const int* in_sizes, int n_in,
                              void* d_out, int out_size)
{
    const float* x         = (const float*)d_in[0];
    const float* enc_w1    = (const float*)d_in[1];
    const float* enc_b1    = (const float*)d_in[2];
    const float* enc_w2    = (const float*)d_in[3];
    const float* enc_b2    = (const float*)d_in[4];
    const float* in_proj_w = (const float*)d_in[5];
    const float* conv_w    = (const float*)d_in[6];
    const float* conv_b    = (const float*)d_in[7];
    const float* x_proj_w  = (const float*)d_in[8];
    const float* dt_proj_w = (const float*)d_in[9];
    const float* dt_proj_b = (const float*)d_in[10];
    const float* A_log     = (const float*)d_in[11];
    const float* D_param   = (const float*)d_in[12];
    const float* out_proj_w= (const float*)d_in[13];
    const float* dec_w1    = (const float*)d_in[14];
    const float* dec_b1    = (const float*)d_in[15];
    const float* dec_w2    = (const float*)d_in[16];
    const float* dec_b2    = (const float*)d_in[17];
    float* out = (float*)d_out;

    float* pxz  = (float*)sym_addr(g_xz);
    float* pdbl = (float*)sym_addr(g_dbl);
    float* pdel = (float*)sym_addr(g_delta);
    u16* pxh  = (u16*)sym_addr(x_h);   u16* pxl  = (u16*)sym_addr(x_l);
    u16* phh  = (u16*)sym_addr(h_h);   u16* phl  = (u16*)sym_addr(h_l);
    u16* pus  = (u16*)sym_addr(u_s);
    u16* pxmh = (u16*)sym_addr(xm_hb); u16* pxml = (u16*)sym_addr(xm_lb);
    u16* pdbh = (u16*)sym_addr(db_hb); u16* pdbll= (u16*)sym_addr(db_lb);
    u16* pys  = (u16*)sym_addr(y_s);
    u16* po1h = (u16*)sym_addr(o1_hb); u16* po1l = (u16*)sym_addr(o1_lb);
    u16* ph2h = (u16*)sym_addr(h2_hb); u16* ph2l = (u16*)sym_addr(h2_lb);
    u16* pw1h = (u16*)sym_addr(w1_hb); u16* pw1l = (u16*)sym_addr(w1_lb);
    u16* pw2h = (u16*)sym_addr(w2_hb); u16* pw2l = (u16*)sym_addr(w2_lb);
    u16* pwip = (u16*)sym_addr(wip_s);
    u16* pwxh = (u16*)sym_addr(wxp_hb);u16* pwxl = (u16*)sym_addr(wxp_lb);
    u16* pwdh = (u16*)sym_addr(wdt_hb);u16* pwdl = (u16*)sym_addr(wdt_lb);
    u16* pwop = (u16*)sym_addr(wop_s);
    u16* pd1h = (u16*)sym_addr(wd1_hb);u16* pd1l = (u16*)sym_addr(wd1_lb);
    u16* pd2h = (u16*)sym_addr(wd2_hb);u16* pd2l = (u16*)sym_addr(wd2_lb);

    // dynamic smem sizes (bytes)
    const int SM_SPLIT_128 = 2 * 2*(128+128)*40*2;   // 81920
    const int SM_SPLIT_64  = 2 * 2*(128+64)*40*2;    // 61440
    const int SM_PLAIN_128 = 4 * (128+128)*40*2;     // 81920

    cudaFuncSetAttribute((const void*)gemm16<128,128,2,4,ACT_RELU,1,EPI_BFHL,2>,
                         cudaFuncAttributeMaxDynamicSharedMemorySize, SM_SPLIT_128);
    cudaFuncSetAttribute((const void*)gemm16<128,128,2,4,ACT_NONE,1,EPI_FP16S,2>,
                         cudaFuncAttributeMaxDynamicSharedMemorySize, SM_SPLIT_128);
    cudaFuncSetAttribute((const void*)gemm16<128,128,2,4,ACT_NONE,0,EPI_F32,4>,
                         cudaFuncAttributeMaxDynamicSharedMemorySize, SM_PLAIN_128);
    cudaFuncSetAttribute((const void*)gemm16<128,64,4,2,ACT_NONE,1,EPI_F32_BFHL,2>,
                         cudaFuncAttributeMaxDynamicSharedMemorySize, SM_SPLIT_64);
    cudaFuncSetAttribute((const void*)gemm16<128,128,2,4,ACT_SOFTPLUS,1,EPI_F32,2>,
                         cudaFuncAttributeMaxDynamicSharedMemorySize, SM_SPLIT_128);
    cudaFuncSetAttribute((const void*)gemm16<128,128,2,4,ACT_NONE,0,EPI_BFHL,4>,
                         cudaFuncAttributeMaxDynamicSharedMemorySize, SM_PLAIN_128);
    cudaFuncSetAttribute((const void*)gemm16<128,128,2,4,ACT_RELU,1,EPI_BFHL,2>,
                         cudaFuncAttributeMaxDynamicSharedMemorySize, SM_SPLIT_128);
    cudaFuncSetAttribute((const void*)gemm16<128,64,4,2,ACT_NONE,1,EPI_F32,2>,
                         cudaFuncAttributeMaxDynamicSharedMemorySize, SM_SPLIT_64);

    // ---- converters (inputs + weights only; activations converted in epilogues) ----
    cvt_bf<<<(MTOT*DIN + 255)/256, 256>>>(x, pxh, pxl, MTOT*DIN);
    cvt_bf<<<(HID*DIN + 255)/256, 256>>>(enc_w1, pw1h, pw1l, HID*DIN);
    cvt_bf<<<(DMODEL*HID + 255)/256, 256>>>(enc_w2, pw2h, pw2l, DMODEL*HID);
    cvt_bf<<<(64*DINNER + 255)/256, 256>>>(x_proj_w, pwxh, pwxl, 64*DINNER);
    cvt_bf<<<(DINNER*DTRANK + 255)/256, 256>>>(dt_proj_w, pwdh, pwdl, DINNER*DTRANK);
    cvt_bf<<<(HID*DMODEL + 255)/256, 256>>>(dec_w1, pd1h, pd1l, HID*DMODEL);
    cvt_bf<<<(DOUTD*HID + 255)/256, 256>>>(dec_w2, pd2h, pd2l, DOUTD*HID);
    cvt_h<<<(2*DINNER*DMODEL + 255)/256, 256>>>(in_proj_w, pwip, 64.f, 2*DINNER*DMODEL);
    cvt_h<<<(DMODEL*DINNER + 255)/256, 256>>>(out_proj_w, pwop, 64.f, DMODEL*DINNER);

    // 1. enc1: relu -> h (bf16 hi/lo)      [16384,256] K=64
    gemm16<128,128,2,4,ACT_RELU,1,EPI_BFHL,2><<<dim3(HID/128, MTOT/128), 256, SM_SPLIT_128>>>(
        pxh, pxl, pw1h, pw1l, enc_b1, phh, phl, nullptr, MTOT, HID, DIN, DIN, 1.f, 0.f);

    // 2. enc2: u -> fp16*1024              [16384,512] K=256
    gemm16<128,128,2,4,ACT_NONE,1,EPI_FP16S,2><<<dim3(DMODEL/128, MTOT/128), 256, SM_SPLIT_128>>>(
        phh, phl, pw2h, pw2l, enc_b2, pus, nullptr, nullptr, MTOT, DMODEL, HID, HID, 1.f, 1024.f);

    // 3. in_proj: xz (fp32)                [16384,2048] K=512, scaled fp16
    gemm16<128,128,2,4,ACT_NONE,0,EPI_F32,4><<<dim3(2*DINNER/128, MTOT/128), 256, SM_PLAIN_128>>>(
        pus, nullptr, pwip, nullptr, nullptr, pxz, nullptr, nullptr,
        MTOT, 2*DINNER, DMODEL, DMODEL, 1.f/65536.f, 0.f);

    // 4. conv + silu -> g_xm + xm bf16 hi/lo
    conv_silu_kernel<<<(MTOT*DINNER)/256, 256>>>(conv_w, conv_b);

    // 5. x_proj: dbl (fp32 + bf16 hi/lo)   [16384,64] K=1024
    gemm16<128,64,4,2,ACT_NONE,1,EPI_F32_BFHL,2><<<dim3(1, MTOT/128), 256, SM_SPLIT_64>>>(
        pxmh, pxml, pwxh, pwxl, nullptr, pdbl, pdbh, pdbll, MTOT, 64, DINNER, DINNER, 1.f, 0.f);

    // 6. dt_proj + softplus -> delta (fp32) [16384,1024] K=32, lda=64
    gemm16<128,128,2,4,ACT_SOFTPLUS,1,EPI_F32,2><<<dim3(DINNER/128, MTOT/128), 256, SM_SPLIT_128>>>(
        pdbh, pdbll, pwdh, pwdl, dt_proj_b, pdel, nullptr, nullptr, MTOT, DINNER, DTRANK, 64, 1.f, 0.f);

    // 7. scan + gate -> y (fp16*4096)
    scan_kernel<<<(BATCH*DINNER*DSTATE)/256, 256>>>(A_log, D_param);

    // 8. out_proj: o1 (bf16 hi/lo)         [16384,512] K=1024, scaled fp16
    gemm16<128,128,2,4,ACT_NONE,0,EPI_BFHL,4><<<dim3(DMODEL/128, MTOT/128), 256, SM_PLAIN_128>>>(
        pys, nullptr, pwop, nullptr, nullptr, po1h, po1l, nullptr,
        MTOT, DMODEL, DINNER, DINNER, 1.f/262144.f, 0.f);

    // 9. dec1: relu -> h2 (bf16 hi/lo)     [16384,256] K=512
    gemm16<128,128,2,4,ACT_RELU,1,EPI_BFHL,2><<<dim3(HID/128, MTOT/128), 256, SM_SPLIT_128>>>(
        po1h, po1l, pd1h, pd1l, dec_b1, ph2h, ph2l, nullptr, MTOT, HID, DMODEL, DMODEL, 1.f, 0.f);

    // 10. dec2 -> out (fp32)               [16384,64] K=256
    gemm16<128,64,4,2,ACT_NONE,1,EPI_F32,2><<<dim3(1, MTOT/128), 256, SM_SPLIT_64>>>(
        ph2h, ph2l, pd2h, pd2l, dec_b2, out, nullptr, nullptr, MTOT, DOUTD, HID, HID, 1.f, 0.f);
}

// round 15
// speedup vs baseline: 1.5317x; 1.0020x over previous
#include <cuda_runtime.h>
#include <cuda_bf16.h>
#include <cuda_fp16.h>
#include <math.h>
#include <stdint.h>

#define BATCH  8
#define SEQ    2048
#define MTOT   (BATCH*SEQ)      // 16384
#define DIN    64
#define HID    256
#define DMODEL 512
#define DINNER 1024
#define DSTATE 16
#define DTRANK 32
#define DCONV  4
#define DOUTD  64

typedef unsigned short u16;

// ---------------- fp32 scratch ----------------
__device__ float g_xz   [MTOT*2*DINNER];   // (xm | z)
__device__ float g_xm   [MTOT*DINNER];
__device__ float g_dbl  [MTOT*64];         // [dt(32)|B(16)|C(16)]
__device__ float g_delta[MTOT*DINNER];

// ---------------- 16-bit pre-converted operands ----------------
__device__ u16 x_h [MTOT*DIN],    x_l [MTOT*DIN];      // bf16 hi/lo
__device__ u16 h_s [MTOT*HID];                         // fp16 * 256
__device__ u16 u_s [MTOT*DMODEL];                      // fp16 * 1024
__device__ u16 xm_hb[MTOT*DINNER], xm_lb[MTOT*DINNER];
__device__ u16 db_hb[MTOT*64],     db_lb[MTOT*64];
__device__ u16 y_s [MTOT*DINNER];                      // fp16 * 4096
__device__ u16 o1_s[MTOT*DMODEL];                      // fp16 * 2048
__device__ u16 h2_hb[MTOT*HID],    h2_lb[MTOT*HID];
// weights
__device__ u16 w1_hb[HID*DIN],        w1_lb[HID*DIN];
__device__ u16 w2_s [DMODEL*HID];                      // fp16 * 64
__device__ u16 wip_s[2*DINNER*DMODEL];                 // fp16 * 64
__device__ u16 wxp_hb[64*DINNER],     wxp_lb[64*DINNER];
__device__ u16 wdt_hb[DINNER*DTRANK], wdt_lb[DINNER*DTRANK];
__device__ u16 wop_s[DMODEL*DINNER];                   // fp16 * 64
__device__ u16 wd1_s[HID*DMODEL];                      // fp16 * 64
__device__ u16 wd2_hb[DOUTD*HID],     wd2_lb[DOUTD*HID];

enum Act { ACT_NONE = 0, ACT_RELU = 1, ACT_SOFTPLUS = 2 };
enum Epi { EPI_F32 = 0, EPI_BFHL = 1, EPI_FP16S = 2, EPI_F32_BFHL = 3 };

// ---------------- helpers ----------------
__device__ __forceinline__ u16 f2bf(float v) {
    __nv_bfloat16 b = __float2bfloat16(v);
    return *(u16*)&b;
}
__device__ __forceinline__ float bf2f(u16 b) {
    __nv_bfloat16 t = *(__nv_bfloat16*)&b;
    return __bfloat162float(t);
}
__device__ __forceinline__ u16 f2h(float v) {
    __half h = __float2half_rn(v);
    return *(u16*)&h;
}

__device__ __forceinline__ void mma16_bf(float c[4], const uint32_t a[4], const uint32_t b[2]) {
    asm volatile(
        "mma.sync.aligned.m16n8k16.row.col.f32.bf16.bf16.f32 "
        "{%0,%1,%2,%3}, {%4,%5,%6,%7}, {%8,%9}, {%0,%1,%2,%3};\n"
        : "+f"(c[0]), "+f"(c[1]), "+f"(c[2]), "+f"(c[3])
        : "r"(a[0]), "r"(a[1]), "r"(a[2]), "r"(a[3]), "r"(b[0]), "r"(b[1]));
}
__device__ __forceinline__ void mma16_fp(float c[4], const uint32_t a[4], const uint32_t b[2]) {
    asm volatile(
        "mma.sync.aligned.m16n8k16.row.col.f32.f16.f16.f32 "
        "{%0,%1,%2,%3}, {%4,%5,%6,%7}, {%8,%9}, {%0,%1,%2,%3};\n"
        : "+f"(c[0]), "+f"(c[1]), "+f"(c[2]), "+f"(c[3])
        : "r"(a[0]), "r"(a[1]), "r"(a[2]), "r"(a[3]), "r"(b[0]), "r"(b[1]));
}
__device__ __forceinline__ void ldsm4(uint32_t* r, uint32_t saddr) {
    asm volatile("ldmatrix.sync.aligned.m8n8.x4.shared.b16 {%0,%1,%2,%3}, [%4];"
                 : "=r"(r[0]), "=r"(r[1]), "=r"(r[2]), "=r"(r[3]) : "r"(saddr));
}
__device__ __forceinline__ void cp16(void* sdst, const void* gsrc) {
    uint32_t d = (uint32_t)__cvta_generic_to_shared(sdst);
    asm volatile("cp.async.cg.shared.global [%0], [%1], 16;\n" :: "r"(d), "l"(gsrc));
}
__device__ __forceinline__ void cp_commit() { asm volatile("cp.async.commit_group;\n"); }
template<int N> __device__ __forceinline__ void cp_wait() {
    asm volatile("cp.async.wait_group %0;\n" :: "n"(N));
}

// ---------------- cp.async multi-stage 16-bit GEMM ----------------
// C = act(inv_s * A*W^T + bias). Operands pre-converted in global (16-bit).
// SPLIT=1: bf16 hi/lo, 3 bf16 MMAs per k16. SPLIT=0: scaled fp16, 1 MMA.
template<int BM,int BN,int WARPS_M,int WARPS_N,int ACT,int SPLIT,int EPI,int STAGES>
__global__ void __launch_bounds__(WARPS_M*WARPS_N*32, 2)
gemm16(const u16* __restrict__ Ah, const u16* __restrict__ Al,
       const u16* __restrict__ Wh, const u16* __restrict__ Wl,
       const float* __restrict__ bias,
       void* C0v, void* C1v, void* C2v,
       int M, int N, int K, int lda, float inv_s, float oscale)
{
    constexpr int BK = 32, SK2 = 40;
    constexpr int THREADS = WARPS_M*WARPS_N*32;
    constexpr int WMt = BM/WARPS_M, WNt = BN/WARPS_N;
    constexpr int MM = WMt/16, MN = WNt/8;
    constexpr int A_SH = BM*SK2, B_SH = BN*SK2;
    constexpr int STAGE = (A_SH + B_SH) * (SPLIT ? 2 : 1);
    static_assert(MN % 2 == 0, "MN even");

    extern __shared__ u16 sm16[];

    const int tid  = threadIdx.x;
    const int lane = tid & 31;
    const int warp = tid >> 5;
    const int g    = lane >> 2;
    const int c4   = lane & 3;
    const int wrow = (warp / WARPS_N) * WMt;
    const int wcol = (warp % WARPS_N) * WNt;
    const int bm   = blockIdx.y * BM;
    const int bn   = blockIdx.x * BN;
    const int KT   = K / BK;

    const int a_m  = lane & 15;
    const int a_kc = (lane & 16) >> 1;
    const int b_nt = (lane >> 4) & 1;
    const int b_n  = lane & 7;
    const int b_kc = lane & 8;

    float acc[MM][MN][4];
#pragma unroll
    for (int i = 0; i < MM; i++)
#pragma unroll
        for (int j = 0; j < MN; j++)
#pragma unroll
            for (int q = 0; q < 4; q++) acc[i][j][q] = 0.f;

    auto fill = [&](int kt) {
        if (kt < KT) {
            const int k0 = kt * BK;
            u16* base = sm16 + (kt % STAGES) * STAGE;
            u16* dA = base;
            u16* dB = base + A_SH;
#pragma unroll
            for (int i = tid; i < BM*4; i += THREADS) {
                int r = i >> 2, c = (i & 3) * 8;
                cp16(dA + r*SK2 + c, Ah + (size_t)(bm + r)*lda + k0 + c);
            }
#pragma unroll
            for (int i = tid; i < BN*4; i += THREADS) {
                int r = i >> 2, c = (i & 3) * 8;
                cp16(dB + r*SK2 + c, Wh + (size_t)(bn + r)*K + k0 + c);
            }
            if (SPLIT) {
                u16* dAl = base + A_SH + B_SH;
                u16* dBl = dAl + A_SH;
#pragma unroll
                for (int i = tid; i < BM*4; i += THREADS) {
                    int r = i >> 2, c = (i & 3) * 8;
                    cp16(dAl + r*SK2 + c, Al + (size_t)(bm + r)*lda + k0 + c);
                }
#pragma unroll
                for (int i = tid; i < BN*4; i += THREADS) {
                    int r = i >> 2, c = (i & 3) * 8;
                    cp16(dBl + r*SK2 + c, Wl + (size_t)(bn + r)*K + k0 + c);
                }
            }
        }
        cp_commit();
    };

#pragma unroll
    for (int s = 0; s < STAGES-1; s++) fill(s);

    for (int kt = 0; kt < KT; kt++) {
        cp_wait<STAGES-2>();
        __syncthreads();
        fill(kt + STAGES - 1);

        u16* base = sm16 + (kt % STAGES) * STAGE;
        const uint32_t sAh = (uint32_t)__cvta_generic_to_shared(base);
        const uint32_t sBh = sAh + A_SH*2;
        const uint32_t sAl = sBh + B_SH*2;
        const uint32_t sBl = sAl + A_SH*2;

#pragma unroll
        for (int kk = 0; kk < BK; kk += 16) {
            uint32_t ah[MM][4], al[MM][4];
#pragma unroll
            for (int mi = 0; mi < MM; mi++) {
                uint32_t off = (uint32_t)(((wrow + mi*16 + a_m)*SK2 + kk + a_kc) * 2);
                ldsm4(ah[mi], sAh + off);
                if (SPLIT) ldsm4(al[mi], sAl + off);
            }
            uint32_t bh[MN][2], bl[MN][2];
#pragma unroll
            for (int ni = 0; ni < MN; ni += 2) {
                uint32_t off = (uint32_t)(((wcol + (ni + b_nt)*8 + b_n)*SK2 + kk + b_kc) * 2);
                uint32_t rh[4];
                ldsm4(rh, sBh + off);
                bh[ni][0] = rh[0];   bh[ni][1] = rh[1];
                bh[ni+1][0] = rh[2]; bh[ni+1][1] = rh[3];
                if (SPLIT) {
                    uint32_t rl[4];
                    ldsm4(rl, sBl + off);
                    bl[ni][0] = rl[0];   bl[ni][1] = rl[1];
                    bl[ni+1][0] = rl[2]; bl[ni+1][1] = rl[3];
                }
            }
#pragma unroll
            for (int ni = 0; ni < MN; ni++)
#pragma unroll
                for (int mi = 0; mi < MM; mi++) {
                    if (SPLIT) {
                        mma16_bf(acc[mi][ni], al[mi], bh[ni]);
                        mma16_bf(acc[mi][ni], ah[mi], bl[ni]);
                        mma16_bf(acc[mi][ni], ah[mi], bh[ni]);
                    } else {
                        mma16_fp(acc[mi][ni], ah[mi], bh[ni]);
                    }
                }
        }
        __syncthreads();
    }

    // ---- epilogue ----
#pragma unroll
    for (int mi = 0; mi < MM; mi++) {
        int r0 = bm + wrow + mi*16 + g;
#pragma unroll
        for (int ni = 0; ni < MN; ni++) {
            int col = bn + wcol + ni*8 + 2*c4;
            float b0 = 0.f, b1 = 0.f;
            if (bias) { b0 = bias[col]; b1 = bias[col + 1]; }
            float v[4];
            v[0] = acc[mi][ni][0]*inv_s + b0;
            v[1] = acc[mi][ni][1]*inv_s + b1;
            v[2] = acc[mi][ni][2]*inv_s + b0;
            v[3] = acc[mi][ni][3]*inv_s + b1;
#pragma unroll
            for (int q = 0; q < 4; q++) {
                if (ACT == ACT_RELU)     v[q] = fmaxf(v[q], 0.f);
                if (ACT == ACT_SOFTPLUS) v[q] = (v[q] > 20.f) ? v[q] : log1pf(__expf(v[q]));
            }
            size_t i0 = (size_t)r0*N + col;
            size_t i1 = (size_t)(r0 + 8)*N + col;
            if (EPI == EPI_F32) {
                float* C0 = (float*)C0v;
                *(float2*)(C0 + i0) = make_float2(v[0], v[1]);
                *(float2*)(C0 + i1) = make_float2(v[2], v[3]);
            } else if (EPI == EPI_FP16S) {
                u16* C0 = (u16*)C0v;
                *(uint32_t*)(C0 + i0) = (uint32_t)f2h(v[0]*oscale) | ((uint32_t)f2h(v[1]*oscale) << 16);
                *(uint32_t*)(C0 + i1) = (uint32_t)f2h(v[2]*oscale) | ((uint32_t)f2h(v[3]*oscale) << 16);
            } else {
                u16 hi[4], lo[4];
#pragma unroll
                for (int q = 0; q < 4; q++) {
                    hi[q] = f2bf(v[q]);
                    lo[q] = f2bf(v[q] - bf2f(hi[q]));
                }
                u16* CH = (u16*)((EPI == EPI_F32_BFHL) ? C1v : C0v);
                u16* CL = (u16*)((EPI == EPI_F32_BFHL) ? C2v : C1v);
                *(uint32_t*)(CH + i0) = (uint32_t)hi[0] | ((uint32_t)hi[1] << 16);
                *(uint32_t*)(CH + i1) = (uint32_t)hi[2] | ((uint32_t)hi[3] << 16);
                *(uint32_t*)(CL + i0) = (uint32_t)lo[0] | ((uint32_t)lo[1] << 16);
                *(uint32_t*)(CL + i1) = (uint32_t)lo[2] | ((uint32_t)lo[3] << 16);
                if (EPI == EPI_F32_BFHL) {
                    float* C0 = (float*)C0v;
                    *(float2*)(C0 + i0) = make_float2(v[0], v[1]);
                    *(float2*)(C0 + i1) = make_float2(v[2], v[3]);
                }
            }
        }
    }
}

// ---------------- converters ----------------
__global__ void cvt_bf(const float* __restrict__ s, u16* __restrict__ h,
                       u16* __restrict__ l, int n)
{
    int i = blockIdx.x * blockDim.x + threadIdx.x;
    if (i < n) {
        float v = s[i];
        u16 hb = f2bf(v);
        h[i] = hb;
        l[i] = f2bf(v - bf2f(hb));
    }
}
__global__ void cvt_h(const float* __restrict__ s, u16* __restrict__ d,
                      float scale, int n)
{
    int i = blockIdx.x * blockDim.x + threadIdx.x;
    if (i < n) d[i] = f2h(s[i] * scale);
}

// ---------------- conv1d + bias + SiLU -> fp32 + bf16 hi/lo ----------------
__global__ void conv_silu_kernel(const float* __restrict__ conv_w,
                                 const float* __restrict__ conv_b)
{
    int idx = blockIdx.x * blockDim.x + threadIdx.x;
    if (idx >= MTOT * DINNER) return;
    int d  = idx % DINNER;
    int bt = idx / DINNER;
    int t  = bt % SEQ;
    int b  = bt / SEQ;

    float acc = conv_b[d];
#pragma unroll
    for (int j = 0; j < DCONV; j++) {
        int tt = t - (DCONV - 1) + j;
        if (tt >= 0)
            acc = fmaf(conv_w[d*DCONV + j],
                       g_xz[(size_t)(b*SEQ + tt)*(2*DINNER) + d], acc);
    }
    float sv = acc / (1.f + __expf(-acc));
    size_t o = (size_t)bt*DINNER + d;
    g_xm[o] = sv;
    u16 hb = f2bf(sv);
    xm_hb[o] = hb;
    xm_lb[o] = f2bf(sv - bf2f(hb));
}

// ---------------- selective scan + fused gating -> scaled fp16 ----------------
__global__ void scan_kernel(const float* __restrict__ A_log,
                            const float* __restrict__ D_param)
{
    int gid = blockIdx.x * blockDim.x + threadIdx.x;
    int grp = gid >> 4;
    int s   = gid & 15;
    if (grp >= BATCH * DINNER) return;
    int b = grp / DINNER;
    int d = grp % DINNER;

    const float Av = -__expf(A_log[d*DSTATE + s]);
    const float Dv = D_param[d];
    const float* drow = g_delta + (size_t)b*SEQ*DINNER + d;
    const float* xrow = g_xm    + (size_t)b*SEQ*DINNER + d;
    const float* zrow = g_xz    + (size_t)b*SEQ*(2*DINNER) + DINNER + d;
    const float* dblb = g_dbl   + (size_t)b*SEQ*64;
    u16*         yrow = y_s     + (size_t)b*SEQ*DINNER + d;

    float h = 0.f;
    for (int t = 0; t < SEQ; t++) {
        float dt = drow[(size_t)t*DINNER];
        float xt = xrow[(size_t)t*DINNER];
        float Bt = dblb[t*64 + DTRANK + s];
        float Ct = dblb[t*64 + DTRANK + DSTATE + s];
        float dA = __expf(dt * Av);
        h = fmaf(dA, h, dt * xt * Bt);
        float p = h * Ct;
        p += __shfl_xor_sync(0xffffffffu, p, 8, 16);
        p += __shfl_xor_sync(0xffffffffu, p, 4, 16);
        p += __shfl_xor_sync(0xffffffffu, p, 2, 16);
        p += __shfl_xor_sync(0xffffffffu, p, 1, 16);
        if (s == 0) {
            float z  = zrow[(size_t)t*2*DINNER];
            float yv = p + xt * Dv;
            yrow[(size_t)t*DINNER] = f2h(yv * (z / (1.f + __expf(-z))) * 4096.f);
        }
    }
}

// ---------------- host launch ----------------
static void* sym_addr(const void* symbol)
{
    void* p = nullptr;
    cudaGetSymbolAddress(&p, symbol);
    return p;
}

extern "C" void kernel_launch(void* const* d_in, const int* in_sizes, int n_in,
                              void* d_out, int out_size)
{
    const float* x         = (const float*)d_in[0];
    const float* enc_w1    = (const float*)d_in[1];
    const float* enc_b1    = (const float*)d_in[2];
    const float* enc_w2    = (const float*)d_in[3];
    const float* enc_b2    = (const float*)d_in[4];
    const float* in_proj_w = (const float*)d_in[5];
    const float* conv_w    = (const float*)d_in[6];
    const float* conv_b    = (const float*)d_in[7];
    const float* x_proj_w  = (const float*)d_in[8];
    const float* dt_proj_w = (const float*)d_in[9];
    const float* dt_proj_b = (const float*)d_in[10];
    const float* A_log     = (const float*)d_in[11];
    const float* D_param   = (const float*)d_in[12];
    const float* out_proj_w= (const float*)d_in[13];
    const float* dec_w1    = (const float*)d_in[14];
    const float* dec_b1    = (const float*)d_in[15];
    const float* dec_w2    = (const float*)d_in[16];
    const float* dec_b2    = (const float*)d_in[17];
    float* out = (float*)d_out;

    float* pxz  = (float*)sym_addr(g_xz);
    float* pdbl = (float*)sym_addr(g_dbl);
    float* pdel = (float*)sym_addr(g_delta);
    u16* pxh  = (u16*)sym_addr(x_h);   u16* pxl  = (u16*)sym_addr(x_l);
    u16* phs  = (u16*)sym_addr(h_s);
    u16* pus  = (u16*)sym_addr(u_s);
    u16* pxmh = (u16*)sym_addr(xm_hb); u16* pxml = (u16*)sym_addr(xm_lb);
    u16* pdbh = (u16*)sym_addr(db_hb); u16* pdbll= (u16*)sym_addr(db_lb);
    u16* pys  = (u16*)sym_addr(y_s);
    u16* po1s = (u16*)sym_addr(o1_s);
    u16* ph2h = (u16*)sym_addr(h2_hb); u16* ph2l = (u16*)sym_addr(h2_lb);
    u16* pw1h = (u16*)sym_addr(w1_hb); u16* pw1l = (u16*)sym_addr(w1_lb);
    u16* pw2s = (u16*)sym_addr(w2_s);
    u16* pwip = (u16*)sym_addr(wip_s);
    u16* pwxh = (u16*)sym_addr(wxp_hb);u16* pwxl = (u16*)sym_addr(wxp_lb);
    u16* pwdh = (u16*)sym_addr(wdt_hb);u16* pwdl = (u16*)sym_addr(wdt_lb);
    u16* pwop = (u16*)sym_addr(wop_s);
    u16* pd1s = (u16*)sym_addr(wd1_s);
    u16* pd2h = (u16*)sym_addr(wd2_hb);u16* pd2l = (u16*)sym_addr(wd2_lb);

    // dynamic smem sizes (bytes)
    const int SM_SPLIT_128 = 2 * 2*(128+128)*40*2;   // 81920
    const int SM_SPLIT_64  = 2 * 2*(128+64)*40*2;    // 61440
    const int SM_PLAIN_128 = 4 * (128+128)*40*2;     // 81920

    cudaFuncSetAttribute((const void*)gemm16<128,128,2,4,ACT_RELU,1,EPI_FP16S,2>,
                         cudaFuncAttributeMaxDynamicSharedMemorySize, SM_SPLIT_128);
    cudaFuncSetAttribute((const void*)gemm16<128,128,2,4,ACT_NONE,0,EPI_FP16S,4>,
                         cudaFuncAttributeMaxDynamicSharedMemorySize, SM_PLAIN_128);
    cudaFuncSetAttribute((const void*)gemm16<128,128,2,4,ACT_NONE,0,EPI_F32,4>,
                         cudaFuncAttributeMaxDynamicSharedMemorySize, SM_PLAIN_128);
    cudaFuncSetAttribute((const void*)gemm16<128,64,4,2,ACT_NONE,1,EPI_F32_BFHL,2>,
                         cudaFuncAttributeMaxDynamicSharedMemorySize, SM_SPLIT_64);
    cudaFuncSetAttribute((const void*)gemm16<128,128,2,4,ACT_SOFTPLUS,1,EPI_F32,2>,
                         cudaFuncAttributeMaxDynamicSharedMemorySize, SM_SPLIT_128);
    cudaFuncSetAttribute((const void*)gemm16<128,128,2,4,ACT_RELU,0,EPI_BFHL,4>,
                         cudaFuncAttributeMaxDynamicSharedMemorySize, SM_PLAIN_128);
    cudaFuncSetAttribute((const void*)gemm16<128,64,4,2,ACT_NONE,1,EPI_F32,2>,
                         cudaFuncAttributeMaxDynamicSharedMemorySize, SM_SPLIT_64);

    // ---- launch order arranged so ncu (-s 5 -c 1) profiles launch #6 = enc2 GEMM ----
    // 1-4: converters needed by enc1/enc2
    cvt_bf<<<(MTOT*DIN + 255)/256, 256>>>(x, pxh, pxl, MTOT*DIN);               // 1
    cvt_bf<<<(HID*DIN + 255)/256, 256>>>(enc_w1, pw1h, pw1l, HID*DIN);          // 2
    cvt_h<<<(DMODEL*HID + 255)/256, 256>>>(enc_w2, pw2s, 64.f, DMODEL*HID);     // 3
    cvt_h<<<(2*DINNER*DMODEL + 255)/256, 256>>>(in_proj_w, pwip, 64.f, 2*DINNER*DMODEL); // 4

    // 5. enc1: relu -> h (fp16*256)        [16384,256] K=64   (bf16x3)
    gemm16<128,128,2,4,ACT_RELU,1,EPI_FP16S,2><<<dim3(HID/128, MTOT/128), 256, SM_SPLIT_128>>>(
        pxh, pxl, pw1h, pw1l, enc_b1, phs, nullptr, nullptr, MTOT, HID, DIN, DIN, 1.f, 256.f);

    // 6. enc2: u -> fp16*1024              [16384,512] K=256  (plain fp16: A*256, W*64)  [PROFILED]
    gemm16<128,128,2,4,ACT_NONE,0,EPI_FP16S,4><<<dim3(DMODEL/128, MTOT/128), 256, SM_PLAIN_128>>>(
        phs, nullptr, pw2s, nullptr, enc_b2, pus, nullptr, nullptr,
        MTOT, DMODEL, HID, HID, 1.f/16384.f, 1024.f);

    // remaining converters
    cvt_bf<<<(64*DINNER + 255)/256, 256>>>(x_proj_w, pwxh, pwxl, 64*DINNER);
    cvt_bf<<<(DINNER*DTRANK + 255)/256, 256>>>(dt_proj_w, pwdh, pwdl, DINNER*DTRANK);
    cvt_h<<<(DMODEL*DINNER + 255)/256, 256>>>(out_proj_w, pwop, 64.f, DMODEL*DINNER);
    cvt_h<<<(HID*DMODEL + 255)/256, 256>>>(dec_w1, pd1s, 64.f, HID*DMODEL);
    cvt_bf<<<(DOUTD*HID + 255)/256, 256>>>(dec_w2, pd2h, pd2l, DOUTD*HID);

    // in_proj: xz (fp32)                   [16384,2048] K=512 (plain fp16: A*1024, W*64)
    gemm16<128,128,2,4,ACT_NONE,0,EPI_F32,4><<<dim3(2*DINNER/128, MTOT/128), 256, SM_PLAIN_128>>>(
        pus, nullptr, pwip, nullptr, nullptr, pxz, nullptr, nullptr,
        MTOT, 2*DINNER, DMODEL, DMODEL, 1.f/65536.f, 0.f);

    // conv + silu -> g_xm + xm bf16 hi/lo
    conv_silu_kernel<<<(MTOT*DINNER)/256, 256>>>(conv_w, conv_b);

    // x_proj: dbl (fp32 + bf16 hi/lo)      [16384,64] K=1024  (bf16x3)
    gemm16<128,64,4,2,ACT_NONE,1,EPI_F32_BFHL,2><<<dim3(1, MTOT/128), 256, SM_SPLIT_64>>>(
        pxmh, pxml, pwxh, pwxl, nullptr, pdbl, pdbh, pdbll, MTOT, 64, DINNER, DINNER, 1.f, 0.f);

    // dt_proj + softplus -> delta (fp32)   [16384,1024] K=32, lda=64 (bf16x3)
    gemm16<128,128,2,4,ACT_SOFTPLUS,1,EPI_F32,2><<<dim3(DINNER/128, MTOT/128), 256, SM_SPLIT_128>>>(
        pdbh, pdbll, pwdh, pwdl, dt_proj_b, pdel, nullptr, nullptr, MTOT, DINNER, DTRANK, 64, 1.f, 0.f);

    // scan + gate -> y (fp16*4096)
    scan_kernel<<<(BATCH*DINNER*DSTATE)/256, 256>>>(A_log, D_param);

    // out_proj: o1 -> fp16*2048            [16384,512] K=1024 (plain fp16: A*4096, W*64)
    gemm16<128,128,2,4,ACT_NONE,0,EPI_FP16S,4><<<dim3(DMODEL/128, MTOT/128), 256, SM_PLAIN_128>>>(
        pys, nullptr, pwop, nullptr, nullptr, po1s, nullptr, nullptr,
        MTOT, DMODEL, DINNER, DINNER, 1.f/262144.f, 2048.f);

    // dec1: relu -> h2 (bf16 hi/lo)        [16384,256] K=512  (plain fp16: A*2048, W*64)
    gemm16<128,128,2,4,ACT_RELU,0,EPI_BFHL,4><<<dim3(HID/128, MTOT/128), 256, SM_PLAIN_128>>>(
        po1s, nullptr, pd1s, nullptr, dec_b1, ph2h, ph2l, nullptr,
        MTOT, HID, DMODEL, DMODEL, 1.f/131072.f, 0.f);

    // dec2 -> out (fp32)                   [16384,64] K=256   (bf16x3)
    gemm16<128,64,4,2,ACT_NONE,1,EPI_F32,2><<<dim3(1, MTOT/128), 256, SM_SPLIT_64>>>(
        ph2h, ph2l, pd2h, pd2l, dec_b2, out, nullptr, nullptr, MTOT, DOUTD, HID, HID, 1.f, 0.f);
}